// round 6
// baseline (speedup 1.0000x reference)
#include <cuda_runtime.h>
#include <math.h>

// Problem constants (shapes are static in the reference)
#define T_TOK 4096     // B*C tokens
#define DIM   1024     // d
#define HID   4096     // 4*d
#define NEXP  8
#define CAP   1280     // floor(2*1.25*4096/8), already even

// ---------------- scratch (device globals; no runtime allocation) -----------
__device__ float g_ebatch[NEXP * CAP * DIM];              // [e, cap, d]    41.9 MB
__device__ float g_h[(size_t)NEXP * CAP * HID];           // [e, cap, 4d]  167.8 MB
__device__ float g_eout[NEXP * CAP * DIM];                // [e, cap, d]    41.9 MB
__device__ int   g_expert[2 * T_TOK];                     // expert id, k-major: [k*T + t]
__device__ int   g_slot[2 * T_TOK];                       // slot in expert batch, or -1 (dropped)
__device__ float g_weight[2 * T_TOK];                     // softmax combine weight
__device__ int   g_tok[NEXP * CAP];                       // token for (e, slot), or -1

// ---------------- 0: reset slot->token map ----------------------------------
__global__ void init_tok_kernel() {
    int i = blockIdx.x * blockDim.x + threadIdx.x;
    if (i < NEXP * CAP) g_tok[i] = -1;
}

// ---------------- 1: router (one warp per token) -----------------------------
__global__ void router_kernel(const float* __restrict__ x,
                              const float* __restrict__ wg) {
    int t = blockIdx.x * blockDim.y + threadIdx.y;
    int lane = threadIdx.x;
    if (t >= T_TOK) return;

    const float* xr = x + (size_t)t * DIM;
    float acc[NEXP];
#pragma unroll
    for (int e = 0; e < NEXP; e++) acc[e] = 0.f;

    for (int j = lane; j < DIM; j += 32) {
        float xv = xr[j];
        const float* w = wg + (size_t)j * NEXP;
#pragma unroll
        for (int e = 0; e < NEXP; e++) acc[e] += xv * w[e];
    }
#pragma unroll
    for (int off = 16; off > 0; off >>= 1)
#pragma unroll
        for (int e = 0; e < NEXP; e++)
            acc[e] += __shfl_down_sync(0xFFFFFFFFu, acc[e], off);

    if (lane == 0) {
        // top-2 (strict > : ties keep lowest index, matching jax.lax.top_k)
        int e0 = 0; float v0 = acc[0];
#pragma unroll
        for (int e = 1; e < NEXP; e++) if (acc[e] > v0) { v0 = acc[e]; e0 = e; }
        int e1 = -1; float v1 = -1e30f;
#pragma unroll
        for (int e = 0; e < NEXP; e++)
            if (e != e0 && acc[e] > v1) { v1 = acc[e]; e1 = e; }
        // softmax over {v0, v1}; v0 >= v1
        float ex = expf(v1 - v0);
        float w0 = 1.f / (1.f + ex);
        float w1 = ex / (1.f + ex);
        g_expert[t] = e0;          g_expert[T_TOK + t] = e1;
        g_weight[t] = w0;          g_weight[T_TOK + t] = w1;
    }
}

// ---------------- 2: ordered rank assignment (capacity dropping) -------------
// Must reproduce cumsum over j = k*T + t ordering exactly.
__global__ void assign_kernel() {
    const int J = 2 * T_TOK;            // 8192
    const int CHUNK = J / 256;          // 32
    __shared__ int scnt[256][NEXP];
    int tid = threadIdx.x;
    int base = tid * CHUNK;

    int cnt[NEXP];
#pragma unroll
    for (int e = 0; e < NEXP; e++) cnt[e] = 0;
    for (int i = 0; i < CHUNK; i++) cnt[g_expert[base + i]]++;
#pragma unroll
    for (int e = 0; e < NEXP; e++) scnt[tid][e] = cnt[e];
    __syncthreads();

    if (tid == 0) {   // serial exclusive scan over 256 thread-chunks (tiny)
        int run[NEXP];
#pragma unroll
        for (int e = 0; e < NEXP; e++) run[e] = 0;
        for (int th = 0; th < 256; th++)
#pragma unroll
            for (int e = 0; e < NEXP; e++) {
                int c = scnt[th][e];
                scnt[th][e] = run[e];
                run[e] += c;
            }
    }
    __syncthreads();

    int run[NEXP];
#pragma unroll
    for (int e = 0; e < NEXP; e++) run[e] = scnt[tid][e];
    for (int i = 0; i < CHUNK; i++) {
        int j = base + i;
        int e = g_expert[j];
        int r = run[e]++;
        if (r < CAP) {
            g_slot[j] = r;
            g_tok[e * CAP + r] = j & (T_TOK - 1);  // j % T_TOK (T is pow2)
        } else {
            g_slot[j] = -1;
        }
    }
}

// ---------------- 3: dispatch — gather token rows into expert batches --------
__global__ void dispatch_kernel(const float* __restrict__ x) {
    int row = blockIdx.x;               // e*CAP + slot
    int t = g_tok[row];
    float4* dst = (float4*)(g_ebatch + (size_t)row * DIM);
    int i = threadIdx.x;                // DIM/4 = 256 float4 per row
    if (t < 0) {
        dst[i] = make_float4(0.f, 0.f, 0.f, 0.f);
    } else {
        const float4* src = (const float4*)(x + (size_t)t * DIM);
        dst[i] = src[i];
    }
}

// ---------------- 4: batched SGEMM, 128x128x8 tiles, optional fused GELU -----
__device__ __forceinline__ float gelu_exact(float v) {
    return 0.5f * v * (1.0f + erff(v * 0.70710678118654752f));
}

template<bool GELU>
__global__ __launch_bounds__(256, 2)
void gemm_kernel(const float* __restrict__ Ab, const float* __restrict__ Bb,
                 float* __restrict__ Cb, int N, int Kd,
                 size_t sA, size_t sB, size_t sC) {
    const float* A = Ab + (size_t)blockIdx.z * sA;   // [M, Kd] row-major
    const float* B = Bb + (size_t)blockIdx.z * sB;   // [Kd, N] row-major
    float*       C = Cb + (size_t)blockIdx.z * sC;   // [M, N]

    int bm = blockIdx.y * 128, bn = blockIdx.x * 128;
    __shared__ float As[8][128];
    __shared__ float Bs[8][128];

    int tid = threadIdx.x;
    int lm = tid >> 1, kq = (tid & 1) * 4;   // A tile: 128 rows x 8 k
    int lk = tid >> 5, nq = (tid & 31) * 4;  // B tile: 8 k x 128 cols
    int ty = tid >> 4, tx = tid & 15;

    float acc[8][8];
#pragma unroll
    for (int i = 0; i < 8; i++)
#pragma unroll
        for (int j = 0; j < 8; j++) acc[i][j] = 0.f;

    for (int k0 = 0; k0 < Kd; k0 += 8) {
        float4 av = *(const float4*)&A[(size_t)(bm + lm) * Kd + k0 + kq];
        As[kq + 0][lm] = av.x;
        As[kq + 1][lm] = av.y;
        As[kq + 2][lm] = av.z;
        As[kq + 3][lm] = av.w;
        *(float4*)&Bs[lk][nq] = *(const float4*)&B[(size_t)(k0 + lk) * N + bn + nq];
        __syncthreads();

#pragma unroll
        for (int kk = 0; kk < 8; kk++) {
            float a[8], b[8];
            *(float4*)(a)     = *(const float4*)&As[kk][ty * 8];
            *(float4*)(a + 4) = *(const float4*)&As[kk][ty * 8 + 4];
            *(float4*)(b)     = *(const float4*)&Bs[kk][tx * 8];
            *(float4*)(b + 4) = *(const float4*)&Bs[kk][tx * 8 + 4];
#pragma unroll
            for (int i = 0; i < 8; i++)
#pragma unroll
                for (int j = 0; j < 8; j++) acc[i][j] += a[i] * b[j];
        }
        __syncthreads();
    }

#pragma unroll
    for (int i = 0; i < 8; i++) {
        size_t base = (size_t)(bm + ty * 8 + i) * N + bn + tx * 8;
#pragma unroll
        for (int j = 0; j < 8; j += 4) {
            float4 v;
            v.x = acc[i][j + 0]; v.y = acc[i][j + 1];
            v.z = acc[i][j + 2]; v.w = acc[i][j + 3];
            if (GELU) {
                v.x = gelu_exact(v.x); v.y = gelu_exact(v.y);
                v.z = gelu_exact(v.z); v.w = gelu_exact(v.w);
            }
            *(float4*)&C[base + j] = v;
        }
    }
}

// ---------------- 5: weighted combine ----------------------------------------
__global__ void combine_kernel(float* __restrict__ out) {
    int t = blockIdx.x;
    int i = threadIdx.x;                 // DIM/4 = 256 float4 per row
    int e0 = g_expert[t],         s0 = g_slot[t];
    int e1 = g_expert[T_TOK + t], s1 = g_slot[T_TOK + t];
    float w0 = g_weight[t];
    float w1 = g_weight[T_TOK + t];

    float4 r = make_float4(0.f, 0.f, 0.f, 0.f);
    if (s0 >= 0) {
        const float4* p = (const float4*)(g_eout + (size_t)(e0 * CAP + s0) * DIM);
        float4 v = p[i];
        r.x += w0 * v.x; r.y += w0 * v.y; r.z += w0 * v.z; r.w += w0 * v.w;
    }
    if (s1 >= 0) {
        const float4* p = (const float4*)(g_eout + (size_t)(e1 * CAP + s1) * DIM);
        float4 v = p[i];
        r.x += w1 * v.x; r.y += w1 * v.y; r.z += w1 * v.z; r.w += w1 * v.w;
    }
    ((float4*)(out + (size_t)t * DIM))[i] = r;
}

// ---------------- launch ------------------------------------------------------
extern "C" void kernel_launch(void* const* d_in, const int* in_sizes, int n_in,
                              void* d_out, int out_size) {
    const float* x      = (const float*)d_in[0];   // [4,1024,1024]
    const float* w_g    = (const float*)d_in[1];   // [1024,8]
    const float* c_fc   = (const float*)d_in[2];   // [8,1024,4096]
    const float* c_proj = (const float*)d_in[3];   // [8,4096,1024]
    float* out = (float*)d_out;

    // Resolve device addresses of scratch symbols (host shadow addresses are
    // NOT valid device pointers — this was the R1 bug).
    void *p_ebatch = nullptr, *p_h = nullptr, *p_eout = nullptr;
    cudaGetSymbolAddress(&p_ebatch, g_ebatch);
    cudaGetSymbolAddress(&p_h,      g_h);
    cudaGetSymbolAddress(&p_eout,   g_eout);
    float* ebatch = (float*)p_ebatch;
    float* hbuf   = (float*)p_h;
    float* eout   = (float*)p_eout;

    init_tok_kernel<<<(NEXP * CAP + 255) / 256, 256>>>();

    dim3 rblk(32, 4);
    router_kernel<<<T_TOK / 4, rblk>>>(x, w_g);

    assign_kernel<<<1, 256>>>();

    dispatch_kernel<<<NEXP * CAP, 256>>>(x);

    // GEMM1 + GELU: [CAP, DIM] @ [DIM, HID] -> g_h, per expert
    {
        dim3 grid(HID / 128, CAP / 128, NEXP);
        gemm_kernel<true><<<grid, 256>>>(ebatch, c_fc, hbuf,
                                         HID, DIM,
                                         (size_t)CAP * DIM, (size_t)DIM * HID,
                                         (size_t)CAP * HID);
    }
    // GEMM2: [CAP, HID] @ [HID, DIM] -> g_eout, per expert
    {
        dim3 grid(DIM / 128, CAP / 128, NEXP);
        gemm_kernel<false><<<grid, 256>>>(hbuf, c_proj, eout,
                                          DIM, HID,
                                          (size_t)CAP * HID, (size_t)HID * DIM,
                                          (size_t)CAP * DIM);
    }

    combine_kernel<<<T_TOK, 256>>>(out);
}

// round 10
// speedup vs baseline: 3.1277x; 3.1277x over previous
#include <cuda_runtime.h>
#include <math.h>
#include <stdint.h>

// Problem constants (static shapes)
#define T_TOK 4096
#define DIM   1024
#define HID   4096
#define NEXP  8
#define CAP   1280

// ===================== helpers ================================================
__device__ __forceinline__ uint32_t smem_u32(const void* p) {
    uint32_t a;
    asm("{ .reg .u64 t; cvta.to.shared.u64 t, %1; cvt.u32.u64 %0, t; }" : "=r"(a) : "l"(p));
    return a;
}

#define CP_ASYNC16(dst, src) \
    asm volatile("cp.async.cg.shared.global [%0], [%1], 16;" :: "r"(dst), "l"(src) : "memory")
#define CP_COMMIT() asm volatile("cp.async.commit_group;" ::: "memory")
#define CP_WAIT_GROUP(n) asm volatile("cp.async.wait_group %0;" :: "n"(n) : "memory")

__device__ __forceinline__ float tf32r(float v) {
    uint32_t o;
    asm("cvt.rna.tf32.f32 %0, %1;" : "=r"(o) : "f"(v));
    return __uint_as_float(o);
}
__device__ __forceinline__ float gelu_exact(float v) {
    return 0.5f * v * (1.0f + erff(v * 0.70710678118654752f));
}

// m16n8k8 TF32 MMA (base PTX, works at sm_103 target -> Blackwell HMMA path)
__device__ __forceinline__ void mma1688(float* c,
                                        uint32_t a0, uint32_t a1, uint32_t a2, uint32_t a3,
                                        uint32_t b0, uint32_t b1) {
    asm volatile(
        "mma.sync.aligned.m16n8k8.row.col.f32.tf32.tf32.f32 "
        "{%0,%1,%2,%3}, {%4,%5,%6,%7}, {%8,%9}, {%0,%1,%2,%3};"
        : "+f"(c[0]), "+f"(c[1]), "+f"(c[2]), "+f"(c[3])
        : "r"(a0), "r"(a1), "r"(a2), "r"(a3), "r"(b0), "r"(b1));
}

// ===================== scratch =================================================
__device__ float g_ebatch[NEXP * CAP * DIM];                 // tf32-rounded A for GEMM1
__device__ float g_h[(size_t)NEXP * CAP * HID];              // tf32-rounded gelu(h)
__device__ float g_eout[NEXP * CAP * DIM];                   // fp32 expert output
__device__ float g_wfc_t[(size_t)NEXP * HID * DIM];          // c_fc^T   [e][4096][1024] tf32
__device__ float g_wproj_t[(size_t)NEXP * DIM * HID];        // c_proj^T [e][1024][4096] tf32
__device__ int   g_expert[2 * T_TOK];
__device__ int   g_slot[2 * T_TOK];
__device__ float g_weight[2 * T_TOK];
__device__ int   g_tok[NEXP * CAP];

// ===================== 0: init ================================================
__global__ void init_tok_kernel() {
    int i = blockIdx.x * blockDim.x + threadIdx.x;
    if (i < NEXP * CAP) g_tok[i] = -1;
}

// ===================== 1: router ==============================================
__global__ void router_kernel(const float* __restrict__ x,
                              const float* __restrict__ wg) {
    int t = blockIdx.x * blockDim.y + threadIdx.y;
    int lane = threadIdx.x;
    if (t >= T_TOK) return;
    const float* xr = x + (size_t)t * DIM;
    float acc[NEXP];
#pragma unroll
    for (int e = 0; e < NEXP; e++) acc[e] = 0.f;
    for (int j = lane; j < DIM; j += 32) {
        float xv = xr[j];
        const float* w = wg + (size_t)j * NEXP;
#pragma unroll
        for (int e = 0; e < NEXP; e++) acc[e] += xv * w[e];
    }
#pragma unroll
    for (int off = 16; off > 0; off >>= 1)
#pragma unroll
        for (int e = 0; e < NEXP; e++)
            acc[e] += __shfl_down_sync(0xFFFFFFFFu, acc[e], off);
    if (lane == 0) {
        int e0 = 0; float v0 = acc[0];
#pragma unroll
        for (int e = 1; e < NEXP; e++) if (acc[e] > v0) { v0 = acc[e]; e0 = e; }
        int e1 = -1; float v1 = -1e30f;
#pragma unroll
        for (int e = 0; e < NEXP; e++)
            if (e != e0 && acc[e] > v1) { v1 = acc[e]; e1 = e; }
        float ex = expf(v1 - v0);
        float w0 = 1.f / (1.f + ex);
        float w1 = ex / (1.f + ex);
        g_expert[t] = e0;          g_expert[T_TOK + t] = e1;
        g_weight[t] = w0;          g_weight[T_TOK + t] = w1;
    }
}

// ===================== 2: ordered rank/capacity ================================
__global__ void assign_kernel() {
    const int J = 2 * T_TOK;
    const int CHUNK = J / 256;
    __shared__ int scnt[256][NEXP];
    int tid = threadIdx.x;
    int base = tid * CHUNK;
    int cnt[NEXP];
#pragma unroll
    for (int e = 0; e < NEXP; e++) cnt[e] = 0;
    for (int i = 0; i < CHUNK; i++) cnt[g_expert[base + i]]++;
#pragma unroll
    for (int e = 0; e < NEXP; e++) scnt[tid][e] = cnt[e];
    __syncthreads();
    if (tid == 0) {
        int run[NEXP];
#pragma unroll
        for (int e = 0; e < NEXP; e++) run[e] = 0;
        for (int th = 0; th < 256; th++)
#pragma unroll
            for (int e = 0; e < NEXP; e++) {
                int c = scnt[th][e];
                scnt[th][e] = run[e];
                run[e] += c;
            }
    }
    __syncthreads();
    int run[NEXP];
#pragma unroll
    for (int e = 0; e < NEXP; e++) run[e] = scnt[tid][e];
    for (int i = 0; i < CHUNK; i++) {
        int j = base + i;
        int e = g_expert[j];
        int r = run[e]++;
        if (r < CAP) {
            g_slot[j] = r;
            g_tok[e * CAP + r] = j & (T_TOK - 1);
        } else {
            g_slot[j] = -1;
        }
    }
}

// ===================== 3: dispatch (tf32 rounding) =============================
__global__ void dispatch_kernel(const float* __restrict__ x) {
    int row = blockIdx.x;
    int t = g_tok[row];
    float4* dst = (float4*)(g_ebatch + (size_t)row * DIM);
    int i = threadIdx.x;
    if (t < 0) {
        dst[i] = make_float4(0.f, 0.f, 0.f, 0.f);
    } else {
        const float4* src = (const float4*)(x + (size_t)t * DIM);
        float4 v = src[i];
        v.x = tf32r(v.x); v.y = tf32r(v.y); v.z = tf32r(v.z); v.w = tf32r(v.w);
        dst[i] = v;
    }
}

// ===================== 3b: weight transpose + tf32 round =======================
// src [K, N] row-major -> dst [N, K] row-major, per expert (blockIdx.z)
__global__ void transpose_round_kernel(const float* __restrict__ src,
                                       float* __restrict__ dst,
                                       int K, int N, size_t sSrc, size_t sDst) {
    const float* S = src + blockIdx.z * sSrc;
    float* D = dst + blockIdx.z * sDst;
    __shared__ float tile[32][33];
    int k0 = blockIdx.y * 32, n0 = blockIdx.x * 32;
    int tx = threadIdx.x, ty = threadIdx.y;
#pragma unroll
    for (int i = 0; i < 32; i += 8)
        tile[ty + i][tx] = S[(size_t)(k0 + ty + i) * N + n0 + tx];
    __syncthreads();
#pragma unroll
    for (int i = 0; i < 32; i += 8)
        D[(size_t)(n0 + ty + i) * K + k0 + tx] = tf32r(tile[tx][ty + i]);
}

// ===================== 4: TF32 mma.sync GEMM ===================================
// C[M,N] = A[M,K] * B[N,K]^T, block tile 128x128, BK=16, 4-stage cp.async.
// SMEM row stride of 20 floats -> conflict-free fragment loads.
#define GSTAGES 4
#define BK 16
#define ROW_F 20                                   // floats per smem row (16 data + 4 pad)
#define TILE_FLOATS (128 * ROW_F)                  // per A or B tile
#define STAGE_FLOATS (2 * TILE_FLOATS)
#define GEMM_SMEM (GSTAGES * STAGE_FLOATS * 4)     // 81920 bytes

template<bool GELU>
__global__ __launch_bounds__(256, 2)
void mma_gemm(const float* __restrict__ Abase, const float* __restrict__ Bbase,
              float* __restrict__ Cbase, int Kdim, int Ndim,
              size_t sA, size_t sB, size_t sC)
{
    extern __shared__ float smem[];
    const float* A = Abase + (size_t)blockIdx.z * sA;
    const float* B = Bbase + (size_t)blockIdx.z * sB;
    float* C = Cbase + (size_t)blockIdx.z * sC;
    int bm = blockIdx.y * 128;
    int bn = blockIdx.x * 128;

    int tid = threadIdx.x;
    int wid = tid >> 5, lane = tid & 31;
    int warp_m = wid >> 2, warp_n = wid & 3;       // 2 x 4 warps
    int lr = lane >> 2, lc = lane & 3;             // fragment row-group / col-in-quad

    float acc[4][4][4];
#pragma unroll
    for (int mt = 0; mt < 4; mt++)
#pragma unroll
        for (int nt = 0; nt < 4; nt++)
#pragma unroll
            for (int q = 0; q < 4; q++) acc[mt][nt][q] = 0.f;

    uint32_t smem_base = smem_u32(smem);

    auto load_stage = [&](int kt) {
        int s = kt & (GSTAGES - 1);
        int k0 = kt * BK;
        uint32_t a_base = smem_base + s * STAGE_FLOATS * 4;
        uint32_t b_base = a_base + TILE_FLOATS * 4;
        // A: 128 rows x 4 x 16B chunks = 512 chunks; 2 per thread
#pragma unroll
        for (int j = 0; j < 2; j++) {
            int c = tid + j * 256;
            int r = c >> 2, seg = c & 3;
            const float* src = A + (size_t)(bm + r) * Kdim + k0 + seg * 4;
            CP_ASYNC16(a_base + (uint32_t)(r * ROW_F * 4 + seg * 16), src);
        }
        // B: 128 rows x 4 chunks
#pragma unroll
        for (int j = 0; j < 2; j++) {
            int c = tid + j * 256;
            int r = c >> 2, seg = c & 3;
            const float* src = B + (size_t)(bn + r) * Kdim + k0 + seg * 4;
            CP_ASYNC16(b_base + (uint32_t)(r * ROW_F * 4 + seg * 16), src);
        }
        CP_COMMIT();
    };

    const int NT = Kdim / BK;

    // prologue: stages 0..GSTAGES-2
#pragma unroll
    for (int kt = 0; kt < GSTAGES - 1; kt++) load_stage(kt);

    for (int kt = 0; kt < NT; kt++) {
        CP_WAIT_GROUP(GSTAGES - 2);                // stage kt resident
        __syncthreads();                           // all warps done with stage (kt-1)%S

        if (kt + GSTAGES - 1 < NT) load_stage(kt + GSTAGES - 1);

        int s = kt & (GSTAGES - 1);
        const float* As = smem + s * STAGE_FLOATS;
        const float* Bs = As + TILE_FLOATS;

#pragma unroll
        for (int step = 0; step < 2; step++) {
            int kb = step * 8 + lc;
            uint32_t af[4][4], bf[4][2];
#pragma unroll
            for (int mt = 0; mt < 4; mt++) {
                int r0 = warp_m * 64 + mt * 16 + lr;
                af[mt][0] = __float_as_uint(As[(r0    ) * ROW_F + kb    ]);
                af[mt][1] = __float_as_uint(As[(r0 + 8) * ROW_F + kb    ]);
                af[mt][2] = __float_as_uint(As[(r0    ) * ROW_F + kb + 4]);
                af[mt][3] = __float_as_uint(As[(r0 + 8) * ROW_F + kb + 4]);
            }
#pragma unroll
            for (int nt = 0; nt < 4; nt++) {
                int n0 = warp_n * 32 + nt * 8 + lr;
                bf[nt][0] = __float_as_uint(Bs[n0 * ROW_F + kb    ]);
                bf[nt][1] = __float_as_uint(Bs[n0 * ROW_F + kb + 4]);
            }
#pragma unroll
            for (int mt = 0; mt < 4; mt++)
#pragma unroll
                for (int nt = 0; nt < 4; nt++)
                    mma1688(acc[mt][nt], af[mt][0], af[mt][1], af[mt][2], af[mt][3],
                            bf[nt][0], bf[nt][1]);
        }
    }

    // epilogue
#pragma unroll
    for (int mt = 0; mt < 4; mt++) {
        int row = bm + warp_m * 64 + mt * 16 + lr;
#pragma unroll
        for (int nt = 0; nt < 4; nt++) {
            int col = bn + warp_n * 32 + nt * 8 + 2 * lc;
            float v0 = acc[mt][nt][0], v1 = acc[mt][nt][1];
            float v2 = acc[mt][nt][2], v3 = acc[mt][nt][3];
            if (GELU) {
                v0 = tf32r(gelu_exact(v0)); v1 = tf32r(gelu_exact(v1));
                v2 = tf32r(gelu_exact(v2)); v3 = tf32r(gelu_exact(v3));
            }
            float2 p0 = make_float2(v0, v1);
            float2 p1 = make_float2(v2, v3);
            *(float2*)&C[(size_t)row * Ndim + col]       = p0;
            *(float2*)&C[(size_t)(row + 8) * Ndim + col] = p1;
        }
    }
}

// ===================== 5: weighted combine ====================================
__global__ void combine_kernel(float* __restrict__ out) {
    int t = blockIdx.x;
    int i = threadIdx.x;
    int e0 = g_expert[t],         s0 = g_slot[t];
    int e1 = g_expert[T_TOK + t], s1 = g_slot[T_TOK + t];
    float w0 = g_weight[t];
    float w1 = g_weight[T_TOK + t];
    float4 r = make_float4(0.f, 0.f, 0.f, 0.f);
    if (s0 >= 0) {
        const float4* p = (const float4*)(g_eout + (size_t)(e0 * CAP + s0) * DIM);
        float4 v = p[i];
        r.x += w0 * v.x; r.y += w0 * v.y; r.z += w0 * v.z; r.w += w0 * v.w;
    }
    if (s1 >= 0) {
        const float4* p = (const float4*)(g_eout + (size_t)(e1 * CAP + s1) * DIM);
        float4 v = p[i];
        r.x += w1 * v.x; r.y += w1 * v.y; r.z += w1 * v.z; r.w += w1 * v.w;
    }
    ((float4*)(out + (size_t)t * DIM))[i] = r;
}

// ===================== launch ==================================================
extern "C" void kernel_launch(void* const* d_in, const int* in_sizes, int n_in,
                              void* d_out, int out_size) {
    const float* x      = (const float*)d_in[0];
    const float* w_g    = (const float*)d_in[1];
    const float* c_fc   = (const float*)d_in[2];
    const float* c_proj = (const float*)d_in[3];
    float* out = (float*)d_out;

    void *p_eb, *p_h, *p_eo, *p_wf, *p_wp;
    cudaGetSymbolAddress(&p_eb, g_ebatch);
    cudaGetSymbolAddress(&p_h,  g_h);
    cudaGetSymbolAddress(&p_eo, g_eout);
    cudaGetSymbolAddress(&p_wf, g_wfc_t);
    cudaGetSymbolAddress(&p_wp, g_wproj_t);
    float* ebatch  = (float*)p_eb;
    float* hbuf    = (float*)p_h;
    float* eout    = (float*)p_eo;
    float* wfc_t   = (float*)p_wf;
    float* wproj_t = (float*)p_wp;

    cudaFuncSetAttribute(mma_gemm<true>,  cudaFuncAttributeMaxDynamicSharedMemorySize, GEMM_SMEM);
    cudaFuncSetAttribute(mma_gemm<false>, cudaFuncAttributeMaxDynamicSharedMemorySize, GEMM_SMEM);

    init_tok_kernel<<<(NEXP * CAP + 255) / 256, 256>>>();

    dim3 rblk(32, 4);
    router_kernel<<<T_TOK / 4, rblk>>>(x, w_g);

    assign_kernel<<<1, 256>>>();

    dispatch_kernel<<<NEXP * CAP, 256>>>(x);

    // weight transposes (+ tf32 rounding)
    {
        dim3 blk(32, 8);
        dim3 g1(HID / 32, DIM / 32, NEXP);   // c_fc [1024,4096] -> [4096,1024]
        transpose_round_kernel<<<g1, blk>>>(c_fc, wfc_t, DIM, HID,
                                            (size_t)DIM * HID, (size_t)HID * DIM);
        dim3 g2(DIM / 32, HID / 32, NEXP);   // c_proj [4096,1024] -> [1024,4096]
        transpose_round_kernel<<<g2, blk>>>(c_proj, wproj_t, HID, DIM,
                                            (size_t)HID * DIM, (size_t)DIM * HID);
    }

    // GEMM1 + GELU: [CAP,1024] x [4096,1024]^T -> g_h [CAP,4096]
    {
        dim3 grid(HID / 128, CAP / 128, NEXP);
        mma_gemm<true><<<grid, 256, GEMM_SMEM>>>(ebatch, wfc_t, hbuf,
                                                 DIM, HID,
                                                 (size_t)CAP * DIM, (size_t)HID * DIM,
                                                 (size_t)CAP * HID);
    }
    // GEMM2: [CAP,4096] x [1024,4096]^T -> g_eout [CAP,1024]
    {
        dim3 grid(DIM / 128, CAP / 128, NEXP);
        mma_gemm<false><<<grid, 256, GEMM_SMEM>>>(hbuf, wproj_t, eout,
                                                  HID, DIM,
                                                  (size_t)CAP * HID, (size_t)DIM * HID,
                                                  (size_t)CAP * DIM);
    }

    combine_kernel<<<T_TOK, 256>>>(out);
}

// round 11
// speedup vs baseline: 5.3918x; 1.7239x over previous
#include <cuda_runtime.h>
#include <cuda_fp16.h>
#include <math.h>
#include <stdint.h>

// Problem constants (static shapes)
#define T_TOK 4096
#define DIM   1024
#define HID   4096
#define NEXP  8
#define CAP   1280

// ===================== helpers ================================================
__device__ __forceinline__ uint32_t smem_u32(const void* p) {
    uint32_t a;
    asm("{ .reg .u64 t; cvta.to.shared.u64 t, %1; cvt.u32.u64 %0, t; }" : "=r"(a) : "l"(p));
    return a;
}

#define CP_ASYNC16(dst, src) \
    asm volatile("cp.async.cg.shared.global [%0], [%1], 16;" :: "r"(dst), "l"(src) : "memory")
#define CP_COMMIT() asm volatile("cp.async.commit_group;" ::: "memory")
#define CP_WAIT_GROUP(n) asm volatile("cp.async.wait_group %0;" :: "n"(n) : "memory")

__device__ __forceinline__ float gelu_exact(float v) {
    return 0.5f * v * (1.0f + erff(v * 0.70710678118654752f));
}

// fp16 m16n8k16 MMA with fp32 accumulate (base PTX sm_70+; HMMA on Blackwell)
__device__ __forceinline__ void mma16816(float* c,
                                         uint32_t a0, uint32_t a1, uint32_t a2, uint32_t a3,
                                         uint32_t b0, uint32_t b1) {
    asm volatile(
        "mma.sync.aligned.m16n8k16.row.col.f32.f16.f16.f32 "
        "{%0,%1,%2,%3}, {%4,%5,%6,%7}, {%8,%9}, {%0,%1,%2,%3};"
        : "+f"(c[0]), "+f"(c[1]), "+f"(c[2]), "+f"(c[3])
        : "r"(a0), "r"(a1), "r"(a2), "r"(a3), "r"(b0), "r"(b1));
}

#define LDMATRIX_X4(r, addr) \
    asm volatile("ldmatrix.sync.aligned.m8n8.x4.shared.b16 {%0,%1,%2,%3}, [%4];" \
                 : "=r"((r)[0]), "=r"((r)[1]), "=r"((r)[2]), "=r"((r)[3]) : "r"(addr))

// ===================== scratch =================================================
__device__ __half g_ebatch[NEXP * CAP * DIM];                // fp16 A for GEMM1
__device__ __half g_h[(size_t)NEXP * CAP * HID];             // fp16 gelu(h) = A for GEMM2
__device__ float  g_eout[NEXP * CAP * DIM];                  // fp32 expert output
__device__ __half g_wfc_t[(size_t)NEXP * HID * DIM];         // c_fc^T   [e][4096][1024]
__device__ __half g_wproj_t[(size_t)NEXP * DIM * HID];       // c_proj^T [e][1024][4096]
__device__ int    g_expert[2 * T_TOK];
__device__ int    g_slot[2 * T_TOK];
__device__ float  g_weight[2 * T_TOK];
__device__ int    g_tok[NEXP * CAP];

// ===================== 0: init ================================================
__global__ void init_tok_kernel() {
    int i = blockIdx.x * blockDim.x + threadIdx.x;
    if (i < NEXP * CAP) g_tok[i] = -1;
}

// ===================== 1: router ==============================================
__global__ void router_kernel(const float* __restrict__ x,
                              const float* __restrict__ wg) {
    int t = blockIdx.x * blockDim.y + threadIdx.y;
    int lane = threadIdx.x;
    if (t >= T_TOK) return;
    const float* xr = x + (size_t)t * DIM;
    float acc[NEXP];
#pragma unroll
    for (int e = 0; e < NEXP; e++) acc[e] = 0.f;
    for (int j = lane; j < DIM; j += 32) {
        float xv = xr[j];
        const float* w = wg + (size_t)j * NEXP;
#pragma unroll
        for (int e = 0; e < NEXP; e++) acc[e] += xv * w[e];
    }
#pragma unroll
    for (int off = 16; off > 0; off >>= 1)
#pragma unroll
        for (int e = 0; e < NEXP; e++)
            acc[e] += __shfl_down_sync(0xFFFFFFFFu, acc[e], off);
    if (lane == 0) {
        int e0 = 0; float v0 = acc[0];
#pragma unroll
        for (int e = 1; e < NEXP; e++) if (acc[e] > v0) { v0 = acc[e]; e0 = e; }
        int e1 = -1; float v1 = -1e30f;
#pragma unroll
        for (int e = 0; e < NEXP; e++)
            if (e != e0 && acc[e] > v1) { v1 = acc[e]; e1 = e; }
        float ex = expf(v1 - v0);
        float w0 = 1.f / (1.f + ex);
        float w1 = ex / (1.f + ex);
        g_expert[t] = e0;          g_expert[T_TOK + t] = e1;
        g_weight[t] = w0;          g_weight[T_TOK + t] = w1;
    }
}

// ===================== 2: ordered rank/capacity ================================
__global__ void assign_kernel() {
    const int J = 2 * T_TOK;
    const int CHUNK = J / 256;
    __shared__ int scnt[256][NEXP];
    int tid = threadIdx.x;
    int base = tid * CHUNK;
    int cnt[NEXP];
#pragma unroll
    for (int e = 0; e < NEXP; e++) cnt[e] = 0;
    for (int i = 0; i < CHUNK; i++) cnt[g_expert[base + i]]++;
#pragma unroll
    for (int e = 0; e < NEXP; e++) scnt[tid][e] = cnt[e];
    __syncthreads();
    if (tid == 0) {
        int run[NEXP];
#pragma unroll
        for (int e = 0; e < NEXP; e++) run[e] = 0;
        for (int th = 0; th < 256; th++)
#pragma unroll
            for (int e = 0; e < NEXP; e++) {
                int c = scnt[th][e];
                scnt[th][e] = run[e];
                run[e] += c;
            }
    }
    __syncthreads();
    int run[NEXP];
#pragma unroll
    for (int e = 0; e < NEXP; e++) run[e] = scnt[tid][e];
    for (int i = 0; i < CHUNK; i++) {
        int j = base + i;
        int e = g_expert[j];
        int r = run[e]++;
        if (r < CAP) {
            g_slot[j] = r;
            g_tok[e * CAP + r] = j & (T_TOK - 1);
        } else {
            g_slot[j] = -1;
        }
    }
}

// ===================== 3: dispatch (fp16 convert) =============================
__global__ void dispatch_kernel(const float* __restrict__ x) {
    int row = blockIdx.x;
    int t = g_tok[row];
    __half2* dst = (__half2*)(g_ebatch + (size_t)row * DIM);
    int i = threadIdx.x;                 // 256 threads, 4 floats each
    if (t < 0) {
        __half2 z = __floats2half2_rn(0.f, 0.f);
        dst[2 * i] = z;
        dst[2 * i + 1] = z;
    } else {
        const float4* src = (const float4*)(x + (size_t)t * DIM);
        float4 v = src[i];
        dst[2 * i]     = __floats2half2_rn(v.x, v.y);
        dst[2 * i + 1] = __floats2half2_rn(v.z, v.w);
    }
}

// ===================== 3b: weight transpose + fp16 convert =====================
// src [K, N] row-major fp32 -> dst [N, K] row-major fp16, per expert (blockIdx.z)
__global__ void transpose_half_kernel(const float* __restrict__ src,
                                      __half* __restrict__ dst,
                                      int K, int N, size_t sSrc, size_t sDst) {
    const float* S = src + blockIdx.z * sSrc;
    __half* D = dst + blockIdx.z * sDst;
    __shared__ float tile[32][33];
    int k0 = blockIdx.y * 32, n0 = blockIdx.x * 32;
    int tx = threadIdx.x, ty = threadIdx.y;
#pragma unroll
    for (int i = 0; i < 32; i += 8)
        tile[ty + i][tx] = S[(size_t)(k0 + ty + i) * N + n0 + tx];
    __syncthreads();
#pragma unroll
    for (int i = 0; i < 32; i += 8)
        D[(size_t)(n0 + ty + i) * K + k0 + tx] = __float2half_rn(tile[tx][ty + i]);
}

// ===================== 4: FP16 mma.sync GEMM ===================================
// C[M,N] = A[M,K] * B[N,K]^T (both fp16 K-major), block 128x128, BK=32, 4 stages.
// SMEM rows: 64B data + 16B pad = 80B  -> ldmatrix phases conflict-free.
#define GSTAGES 4
#define BKH 32
#define ROWB 80
#define TILE_BYTES (128 * ROWB)                    // 10240 per A or B tile
#define STAGE_BYTES (2 * TILE_BYTES)               // 20480
#define GEMM_SMEM (GSTAGES * STAGE_BYTES)          // 81920

template<bool GELU_HALF_OUT>
__global__ __launch_bounds__(256, 2)
void mma_gemm(const __half* __restrict__ Abase, const __half* __restrict__ Bbase,
              void* __restrict__ Cbase, int Kdim, int Ndim,
              size_t sA, size_t sB, size_t sC)
{
    extern __shared__ char smem[];
    const __half* A = Abase + (size_t)blockIdx.z * sA;
    const __half* B = Bbase + (size_t)blockIdx.z * sB;
    int bm = blockIdx.y * 128;
    int bn = blockIdx.x * 128;

    int tid = threadIdx.x;
    int wid = tid >> 5, lane = tid & 31;
    int warp_m = wid >> 2, warp_n = wid & 3;       // 2 x 4 warps; warp tile 64x32
    int lr = lane >> 2, lc = lane & 3;

    float acc[4][4][4];
#pragma unroll
    for (int mt = 0; mt < 4; mt++)
#pragma unroll
        for (int nt = 0; nt < 4; nt++)
#pragma unroll
            for (int q = 0; q < 4; q++) acc[mt][nt][q] = 0.f;

    uint32_t smem_base = smem_u32(smem);

    auto load_stage = [&](int kt) {
        int s = kt & (GSTAGES - 1);
        int k0 = kt * BKH;
        uint32_t a_base = smem_base + s * STAGE_BYTES;
        uint32_t b_base = a_base + TILE_BYTES;
        // A: 128 rows x 4 x 16B segs = 512 chunks; 2 per thread
#pragma unroll
        for (int j = 0; j < 2; j++) {
            int c = tid + j * 256;
            int r = c >> 2, seg = c & 3;
            const __half* src = A + (size_t)(bm + r) * Kdim + k0 + seg * 8;
            CP_ASYNC16(a_base + (uint32_t)(r * ROWB + seg * 16), src);
        }
#pragma unroll
        for (int j = 0; j < 2; j++) {
            int c = tid + j * 256;
            int r = c >> 2, seg = c & 3;
            const __half* src = B + (size_t)(bn + r) * Kdim + k0 + seg * 8;
            CP_ASYNC16(b_base + (uint32_t)(r * ROWB + seg * 16), src);
        }
        CP_COMMIT();
    };

    const int NT = Kdim / BKH;

#pragma unroll
    for (int kt = 0; kt < GSTAGES - 1; kt++) load_stage(kt);

    // ldmatrix per-lane row offset: lanes 0-7 rows 0-7 (k-lo), 8-15 rows 8-15 (k-lo),
    // 16-23 rows 0-7 (k-hi), 24-31 rows 8-15 (k-hi)
    uint32_t lm_off = (uint32_t)((lane & 15) * ROWB + (lane >> 4) * 16);

    for (int kt = 0; kt < NT; kt++) {
        CP_WAIT_GROUP(GSTAGES - 2);
        __syncthreads();

        if (kt + GSTAGES - 1 < NT) load_stage(kt + GSTAGES - 1);

        int s = kt & (GSTAGES - 1);
        uint32_t a_base = smem_base + s * STAGE_BYTES + (uint32_t)(warp_m * 64 * ROWB) + lm_off;
        uint32_t b_base = smem_base + s * STAGE_BYTES + TILE_BYTES
                        + (uint32_t)(warp_n * 32 * ROWB) + lm_off;

#pragma unroll
        for (int step = 0; step < 2; step++) {
            uint32_t koff = (uint32_t)(step * 32);
            uint32_t Af[4][4], Bf[2][4];
#pragma unroll
            for (int mt = 0; mt < 4; mt++)
                LDMATRIX_X4(Af[mt], a_base + (uint32_t)(mt * 16 * ROWB) + koff);
#pragma unroll
            for (int g = 0; g < 2; g++)
                LDMATRIX_X4(Bf[g], b_base + (uint32_t)(g * 16 * ROWB) + koff);
#pragma unroll
            for (int mt = 0; mt < 4; mt++)
#pragma unroll
                for (int nt = 0; nt < 4; nt++) {
                    int g = nt >> 1, hi = nt & 1;
                    uint32_t b0 = hi ? Bf[g][1] : Bf[g][0];
                    uint32_t b1 = hi ? Bf[g][3] : Bf[g][2];
                    mma16816(acc[mt][nt], Af[mt][0], Af[mt][1], Af[mt][2], Af[mt][3], b0, b1);
                }
        }
    }

    // epilogue
#pragma unroll
    for (int mt = 0; mt < 4; mt++) {
        int row = bm + warp_m * 64 + mt * 16 + lr;
#pragma unroll
        for (int nt = 0; nt < 4; nt++) {
            int col = bn + warp_n * 32 + nt * 8 + 2 * lc;
            float v0 = acc[mt][nt][0], v1 = acc[mt][nt][1];
            float v2 = acc[mt][nt][2], v3 = acc[mt][nt][3];
            if (GELU_HALF_OUT) {
                __half* C = (__half*)Cbase + (size_t)blockIdx.z * sC;
                __half2 p0 = __floats2half2_rn(gelu_exact(v0), gelu_exact(v1));
                __half2 p1 = __floats2half2_rn(gelu_exact(v2), gelu_exact(v3));
                *(__half2*)&C[(size_t)row * Ndim + col]       = p0;
                *(__half2*)&C[(size_t)(row + 8) * Ndim + col] = p1;
            } else {
                float* C = (float*)Cbase + (size_t)blockIdx.z * sC;
                *(float2*)&C[(size_t)row * Ndim + col]       = make_float2(v0, v1);
                *(float2*)&C[(size_t)(row + 8) * Ndim + col] = make_float2(v2, v3);
            }
        }
    }
}

// ===================== 5: weighted combine ====================================
__global__ void combine_kernel(float* __restrict__ out) {
    int t = blockIdx.x;
    int i = threadIdx.x;
    int e0 = g_expert[t],         s0 = g_slot[t];
    int e1 = g_expert[T_TOK + t], s1 = g_slot[T_TOK + t];
    float w0 = g_weight[t];
    float w1 = g_weight[T_TOK + t];
    float4 r = make_float4(0.f, 0.f, 0.f, 0.f);
    if (s0 >= 0) {
        const float4* p = (const float4*)(g_eout + (size_t)(e0 * CAP + s0) * DIM);
        float4 v = p[i];
        r.x += w0 * v.x; r.y += w0 * v.y; r.z += w0 * v.z; r.w += w0 * v.w;
    }
    if (s1 >= 0) {
        const float4* p = (const float4*)(g_eout + (size_t)(e1 * CAP + s1) * DIM);
        float4 v = p[i];
        r.x += w1 * v.x; r.y += w1 * v.y; r.z += w1 * v.z; r.w += w1 * v.w;
    }
    ((float4*)(out + (size_t)t * DIM))[i] = r;
}

// ===================== launch ==================================================
extern "C" void kernel_launch(void* const* d_in, const int* in_sizes, int n_in,
                              void* d_out, int out_size) {
    const float* x      = (const float*)d_in[0];
    const float* w_g    = (const float*)d_in[1];
    const float* c_fc   = (const float*)d_in[2];
    const float* c_proj = (const float*)d_in[3];
    float* out = (float*)d_out;

    void *p_eb, *p_h, *p_eo, *p_wf, *p_wp;
    cudaGetSymbolAddress(&p_eb, g_ebatch);
    cudaGetSymbolAddress(&p_h,  g_h);
    cudaGetSymbolAddress(&p_eo, g_eout);
    cudaGetSymbolAddress(&p_wf, g_wfc_t);
    cudaGetSymbolAddress(&p_wp, g_wproj_t);
    __half* ebatch  = (__half*)p_eb;
    __half* hbuf    = (__half*)p_h;
    float*  eout    = (float*)p_eo;
    __half* wfc_t   = (__half*)p_wf;
    __half* wproj_t = (__half*)p_wp;

    cudaFuncSetAttribute(mma_gemm<true>,  cudaFuncAttributeMaxDynamicSharedMemorySize, GEMM_SMEM);
    cudaFuncSetAttribute(mma_gemm<false>, cudaFuncAttributeMaxDynamicSharedMemorySize, GEMM_SMEM);

    init_tok_kernel<<<(NEXP * CAP + 255) / 256, 256>>>();

    dim3 rblk(32, 4);
    router_kernel<<<T_TOK / 4, rblk>>>(x, w_g);

    assign_kernel<<<1, 256>>>();

    dispatch_kernel<<<NEXP * CAP, 256>>>(x);

    // weight transposes (fp32 -> fp16, K-major)
    {
        dim3 blk(32, 8);
        dim3 g1(HID / 32, DIM / 32, NEXP);   // c_fc [1024,4096] -> [4096,1024]
        transpose_half_kernel<<<g1, blk>>>(c_fc, wfc_t, DIM, HID,
                                           (size_t)DIM * HID, (size_t)HID * DIM);
        dim3 g2(DIM / 32, HID / 32, NEXP);   // c_proj [4096,1024] -> [1024,4096]
        transpose_half_kernel<<<g2, blk>>>(c_proj, wproj_t, HID, DIM,
                                           (size_t)HID * DIM, (size_t)DIM * HID);
    }

    // GEMM1 + GELU: [CAP,1024]h x [4096,1024]h^T -> g_h [CAP,4096] fp16
    {
        dim3 grid(HID / 128, CAP / 128, NEXP);
        mma_gemm<true><<<grid, 256, GEMM_SMEM>>>(ebatch, wfc_t, (void*)hbuf,
                                                 DIM, HID,
                                                 (size_t)CAP * DIM, (size_t)HID * DIM,
                                                 (size_t)CAP * HID);
    }
    // GEMM2: [CAP,4096]h x [1024,4096]h^T -> g_eout [CAP,1024] fp32
    {
        dim3 grid(DIM / 128, CAP / 128, NEXP);
        mma_gemm<false><<<grid, 256, GEMM_SMEM>>>(hbuf, wproj_t, (void*)eout,
                                                  HID, DIM,
                                                  (size_t)CAP * HID, (size_t)DIM * HID,
                                                  (size_t)CAP * DIM);
    }

    combine_kernel<<<T_TOK, 256>>>(out);
}